// round 2
// baseline (speedup 1.0000x reference)
#include <cuda_runtime.h>
#include <math.h>

#define Bb 128
#define Tt 512
#define Ee 256
#define Hh 128
#define FOURH 512

// ---------------------------------------------------------------------------
// Scratch (static device globals; no allocation anywhere)
// ---------------------------------------------------------------------------
__device__ float g_xw[(size_t)2 * Tt * Bb * FOURH];   // [dir][t][b][4H]  268MB
__device__ float g_h[2][2][Bb][Hh];                   // [phase][dir][b][h]
__device__ unsigned g_cnt[2];                         // per-direction barrier counters

// ---------------------------------------------------------------------------
// Reset kernel: zero h state (phase buffers) and barrier counters each replay
// ---------------------------------------------------------------------------
__global__ void reset_kernel() {
    int tid = blockIdx.x * blockDim.x + threadIdx.x;
    float* p = &g_h[0][0][0][0];
    const int n = 2 * 2 * Bb * Hh;
    for (int i = tid; i < n; i += gridDim.x * blockDim.x) p[i] = 0.0f;
    if (tid == 0) { g_cnt[0] = 0u; g_cnt[1] = 0u; }
}

// ---------------------------------------------------------------------------
// Projection GEMM: xw[dir][t][b][:] = emb[tokens[b][t]][:] @ W_dir
// M = T*B = 65536 (row = t*128 + b), K = 256, N = 512 per direction.
// BM=128, BN=128, BK=16, 256 threads, 8x8 microtile.
// ---------------------------------------------------------------------------
#define GBM 128
#define GBN 128
#define GBK 16

__global__ __launch_bounds__(256, 2)
void proj_kernel(const int* __restrict__ tokens,
                 const float* __restrict__ emb,
                 const float* __restrict__ Wfw,
                 const float* __restrict__ Wbw) {
    __shared__ float A_sm[GBK][GBM + 4];
    __shared__ float B_sm[GBK][GBN];
    __shared__ int   tok_sm[GBM];

    const int dir = blockIdx.z;
    const float* __restrict__ W = dir ? Wbw : Wfw;
    const int n0 = blockIdx.x * GBN;
    const int m0 = blockIdx.y * GBM;
    const int tid = threadIdx.x;

    if (tid < GBM) {
        int row = m0 + tid;
        int t = row >> 7;       // row / 128
        int b = row & 127;
        tok_sm[tid] = tokens[b * Tt + t];
    }
    __syncthreads();

    const int tr = tid >> 4;    // 0..15 -> rows tr*8..tr*8+7
    const int tc = tid & 15;    // 0..15 -> cols tc*8..tc*8+7

    float acc[8][8];
#pragma unroll
    for (int i = 0; i < 8; i++)
#pragma unroll
        for (int j = 0; j < 8; j++) acc[i][j] = 0.0f;

    for (int kt = 0; kt < Ee; kt += GBK) {
        // Load A tile (gathered embedding rows), store transposed [k][m]
#pragma unroll
        for (int q = tid; q < (GBM * GBK / 4); q += 256) {   // 512 float4s
            int row = q >> 2;           // 0..127
            int kq  = (q & 3) * 4;      // 0,4,8,12
            const float4 v = *(const float4*)(emb + (size_t)tok_sm[row] * Ee + kt + kq);
            A_sm[kq + 0][row] = v.x;
            A_sm[kq + 1][row] = v.y;
            A_sm[kq + 2][row] = v.z;
            A_sm[kq + 3][row] = v.w;
        }
        // Load B tile [k][n]
#pragma unroll
        for (int q = tid; q < (GBK * GBN / 4); q += 256) {   // 512 float4s
            int k  = q >> 5;            // 0..15
            int c4 = (q & 31) * 4;
            *(float4*)&B_sm[k][c4] = *(const float4*)(W + (size_t)(kt + k) * FOURH + n0 + c4);
        }
        __syncthreads();

#pragma unroll
        for (int k = 0; k < GBK; k++) {
            float a_reg[8], b_reg[8];
            *(float4*)&a_reg[0] = *(const float4*)&A_sm[k][tr * 8];
            *(float4*)&a_reg[4] = *(const float4*)&A_sm[k][tr * 8 + 4];
            *(float4*)&b_reg[0] = *(const float4*)&B_sm[k][tc * 8];
            *(float4*)&b_reg[4] = *(const float4*)&B_sm[k][tc * 8 + 4];
#pragma unroll
            for (int i = 0; i < 8; i++)
#pragma unroll
                for (int j = 0; j < 8; j++)
                    acc[i][j] = fmaf(a_reg[i], b_reg[j], acc[i][j]);
        }
        __syncthreads();
    }

    const size_t obase = (size_t)dir * ((size_t)Tt * Bb * FOURH);
#pragma unroll
    for (int i = 0; i < 8; i++) {
        size_t row = (size_t)(m0 + tr * 8 + i);
        float* dst = g_xw + obase + row * FOURH + n0 + tc * 8;
        *(float4*)(dst + 0) = *(float4*)&acc[i][0];
        *(float4*)(dst + 4) = *(float4*)&acc[i][4];
    }
}

// ---------------------------------------------------------------------------
// Persistent bidirectional LSTM recurrence.
// Grid = 128 CTAs: dir = bx>>6; within dir: 16 batch tiles (8 rows) x 4 unit
// tiles (32 units). 128 threads: thread = (bsub 0..3, jl 0..31), owns 2 batch
// rows and 1 hidden unit (all 4 gates). U column tile held in smem (float4,
// gate-interleaved) for the whole kernel. Per-direction grid barrier per step.
// ---------------------------------------------------------------------------
__device__ __forceinline__ float sigmoidf_(float x) {
    return 1.0f / (1.0f + __expf(-x));
}

#define LSTM_SMEM (128 * 32 * sizeof(float4) + 8 * 128 * sizeof(float))

__global__ __launch_bounds__(128, 1)
void lstm_kernel(const float* __restrict__ Ufw,
                 const float* __restrict__ Ubw,
                 const float* __restrict__ bfw,
                 const float* __restrict__ bbw,
                 float* __restrict__ out) {
    extern __shared__ char smem_raw[];
    float4 (*U4)[32]  = (float4(*)[32])smem_raw;                          // [k][jl] 64KB
    float  (*h_sm)[128] = (float(*)[128])(smem_raw + 128 * 32 * sizeof(float4)); // [bl][k] 4KB

    const int bx    = blockIdx.x;
    const int dir   = bx >> 6;
    const int id    = bx & 63;
    const int btile = id >> 2;      // 0..15
    const int utile = id & 3;       // 0..3
    const int tid   = threadIdx.x;
    const int jl    = tid & 31;
    const int bsub  = tid >> 5;     // 0..3

    const int j   = utile * 32 + jl;        // global hidden unit
    const int bl0 = bsub * 2;               // local batch rows
    const int bl1 = bl0 + 1;
    const int b0  = btile * 8 + bl0;
    const int b1  = b0 + 1;

    const float* __restrict__ U    = dir ? Ubw : Ufw;
    const float* __restrict__ bias = dir ? bbw : bfw;

    // Load U column tile: U[k][g*128 + j] -> U4[k][jl] (gate interleaved)
    for (int k = bsub; k < 128; k += 4) {
        const float* up = U + (size_t)k * FOURH + j;
        U4[k][jl] = make_float4(up[0], up[128], up[256], up[384]);
    }
    const float bz0 = bias[0 * Hh + j];
    const float bz1 = bias[1 * Hh + j];
    const float bz2 = bias[2 * Hh + j];
    const float bz3 = bias[3 * Hh + j];

    float c0 = 0.0f, c1 = 0.0f;
    float hout0 = 0.0f, hout1 = 0.0f;

    const size_t xw_dir = (size_t)dir * ((size_t)Tt * Bb * FOURH);

    for (int t = 0; t < Tt; t++) {
        const int tt = dir ? (Tt - 1 - t) : t;
        const int phase = t & 1;

        // Load h_prev tile into smem (L2-coherent reads)
        {
            const float* hp = &g_h[phase][dir][btile * 8][0];
#pragma unroll
            for (int i = tid; i < 8 * 128; i += 128) {
                ((float*)h_sm)[i] = __ldcg(hp + i);
            }
        }

        // Prefetch xw for this step (consumed after the dot loop)
        const float* xwp = g_xw + xw_dir + ((size_t)tt * Bb) * FOURH;
        const float x00 = __ldg(xwp + (size_t)b0 * FOURH + 0 * Hh + j);
        const float x01 = __ldg(xwp + (size_t)b0 * FOURH + 1 * Hh + j);
        const float x02 = __ldg(xwp + (size_t)b0 * FOURH + 2 * Hh + j);
        const float x03 = __ldg(xwp + (size_t)b0 * FOURH + 3 * Hh + j);
        const float x10 = __ldg(xwp + (size_t)b1 * FOURH + 0 * Hh + j);
        const float x11 = __ldg(xwp + (size_t)b1 * FOURH + 1 * Hh + j);
        const float x12 = __ldg(xwp + (size_t)b1 * FOURH + 2 * Hh + j);
        const float x13 = __ldg(xwp + (size_t)b1 * FOURH + 3 * Hh + j);

        __syncthreads();

        float a00 = bz0, a01 = bz1, a02 = bz2, a03 = bz3;
        float a10 = bz0, a11 = bz1, a12 = bz2, a13 = bz3;

#pragma unroll 8
        for (int k = 0; k < 128; k++) {
            const float4 u  = U4[k][jl];
            const float  h0 = h_sm[bl0][k];
            const float  h1 = h_sm[bl1][k];
            a00 = fmaf(h0, u.x, a00); a01 = fmaf(h0, u.y, a01);
            a02 = fmaf(h0, u.z, a02); a03 = fmaf(h0, u.w, a03);
            a10 = fmaf(h1, u.x, a10); a11 = fmaf(h1, u.y, a11);
            a12 = fmaf(h1, u.z, a12); a13 = fmaf(h1, u.w, a13);
        }

        a00 += x00; a01 += x01; a02 += x02; a03 += x03;
        a10 += x10; a11 += x11; a12 += x12; a13 += x13;

        // Gates (Keras order i, f, g, o)
        {
            const float ig = sigmoidf_(a00);
            const float fg = sigmoidf_(a01);
            const float gg = tanhf(a02);
            const float og = sigmoidf_(a03);
            c0 = fg * c0 + ig * gg;
            hout0 = og * tanhf(c0);
        }
        {
            const float ig = sigmoidf_(a10);
            const float fg = sigmoidf_(a11);
            const float gg = tanhf(a12);
            const float og = sigmoidf_(a13);
            c1 = fg * c1 + ig * gg;
            hout1 = og * tanhf(c1);
        }

        // Write hs into out[b][tt][dir*128 + j]
        out[((size_t)b0 * Tt + tt) * 256 + dir * Hh + j] = hout0;
        out[((size_t)b1 * Tt + tt) * 256 + dir * Hh + j] = hout1;
        // Publish h for next step (L2-coherent)
        __stcg(&g_h[phase ^ 1][dir][b0][j], hout0);
        __stcg(&g_h[phase ^ 1][dir][b1][j], hout1);

        if (t < Tt - 1) {
            // Per-direction grid barrier
            __threadfence();
            __syncthreads();
            if (tid == 0) {
                __threadfence();
                atomicAdd(&g_cnt[dir], 1u);
                const unsigned target = 64u * (unsigned)(t + 1);
                while (*((volatile unsigned*)&g_cnt[dir]) < target) { __nanosleep(40); }
                __threadfence();
            }
            __syncthreads();
        }
    }

    // Final states: out layout after [B,T,2H]: h_fw [B,H], c_fw, h_bw, c_bw
    const size_t fin = (size_t)Bb * Tt * 256 + (size_t)dir * 2 * Bb * Hh;
    out[fin + (size_t)b0 * Hh + j]            = hout0;
    out[fin + (size_t)b1 * Hh + j]            = hout1;
    out[fin + Bb * Hh + (size_t)b0 * Hh + j]  = c0;
    out[fin + Bb * Hh + (size_t)b1 * Hh + j]  = c1;
}

// ---------------------------------------------------------------------------
// Launch
// Inputs: tokens[int32 B*T], emb[V*E], W_fw[E*4H], U_fw[H*4H], b_fw[4H],
//         W_bw, U_bw, b_bw
// Output: float32, B*T*2H + 4*B*H
// ---------------------------------------------------------------------------
extern "C" void kernel_launch(void* const* d_in, const int* in_sizes, int n_in,
                              void* d_out, int out_size) {
    const int*   tokens = (const int*)d_in[0];
    const float* emb    = (const float*)d_in[1];
    const float* Wfw    = (const float*)d_in[2];
    const float* Ufw    = (const float*)d_in[3];
    const float* bfw    = (const float*)d_in[4];
    const float* Wbw    = (const float*)d_in[5];
    const float* Ubw    = (const float*)d_in[6];
    const float* bbw    = (const float*)d_in[7];
    float* out = (float*)d_out;

    static bool attr_set = false;
    if (!attr_set) {
        cudaFuncSetAttribute(lstm_kernel,
                             cudaFuncAttributeMaxDynamicSharedMemorySize,
                             (int)LSTM_SMEM);
        attr_set = true;
    }

    reset_kernel<<<64, 256>>>();
    proj_kernel<<<dim3(FOURH / GBN, (Tt * Bb) / GBM, 2), 256>>>(tokens, emb, Wfw, Wbw);
    lstm_kernel<<<128, 128, LSTM_SMEM>>>(Ufw, Ubw, bfw, bbw, out);
}

// round 3
// speedup vs baseline: 1.0604x; 1.0604x over previous
#include <cuda_runtime.h>
#include <math.h>

#define Bb 128
#define Tt 512
#define Ee 256
#define Hh 128
#define FOURH 512

typedef unsigned long long u64t;

// ---------------------------------------------------------------------------
// Static device scratch (no allocation anywhere)
// ---------------------------------------------------------------------------
__device__ float g_xw[(size_t)2 * Tt * Bb * FOURH];   // [dir][t*128+b][4H]
__device__ float g_h[2][2][Bb][Hh];                   // [phase][dir][b][h]
__device__ unsigned g_cnt2[32 * 32];                  // 32 groups, 128B padded

// packed f32x2 helpers
__device__ __forceinline__ u64t pk2(float lo, float hi) {
    u64t r; asm("mov.b64 %0, {%1, %2};" : "=l"(r) : "f"(lo), "f"(hi)); return r;
}
__device__ __forceinline__ void upk2(u64t v, float& lo, float& hi) {
    asm("mov.b64 {%0, %1}, %2;" : "=f"(lo), "=f"(hi) : "l"(v));
}
#define FFMA2(acc, a, b) asm("fma.rn.f32x2 %0, %1, %2, %0;" : "+l"(acc) : "l"(a), "l"(b))

// ---------------------------------------------------------------------------
__global__ void reset_kernel() {
    int tid = blockIdx.x * blockDim.x + threadIdx.x;
    float* p = &g_h[0][0][0][0];
    const int n = 2 * 2 * Bb * Hh;
    for (int i = tid; i < n; i += gridDim.x * blockDim.x) p[i] = 0.0f;
    if (tid < 32 * 32) g_cnt2[tid] = 0u;
}

// ---------------------------------------------------------------------------
// Projection GEMM (FFMA2): xw[dir][t*128+b][:] = emb[tok] @ W_dir
// BM=128, BN=128, BK=16, 256 threads, 8x8 microtile (4 packed col-pairs).
// ---------------------------------------------------------------------------
#define GBM 128
#define GBN 128
#define GBK 16

__global__ __launch_bounds__(256, 2)
void proj_kernel(const int* __restrict__ tokens,
                 const float* __restrict__ emb,
                 const float* __restrict__ Wfw,
                 const float* __restrict__ Wbw) {
    __shared__ __align__(16) float A_sm[GBK][GBM + 4];
    __shared__ __align__(16) float B_sm[GBK][GBN];
    __shared__ int tok_sm[GBM];

    const int dir = blockIdx.z;
    const float* __restrict__ W = dir ? Wbw : Wfw;
    const int n0 = blockIdx.x * GBN;
    const int m0 = blockIdx.y * GBM;
    const int tid = threadIdx.x;

    if (tid < GBM) {
        int row = m0 + tid;
        tok_sm[tid] = tokens[(row & 127) * Tt + (row >> 7)];
    }
    __syncthreads();

    const int tr = tid >> 4;    // row group
    const int tc = tid & 15;    // col group

    __align__(16) u64t acc2[8][4];
#pragma unroll
    for (int i = 0; i < 8; i++)
#pragma unroll
        for (int j = 0; j < 4; j++) acc2[i][j] = 0ull;

    for (int kt = 0; kt < Ee; kt += GBK) {
#pragma unroll
        for (int q = tid; q < (GBM * GBK / 4); q += 256) {
            int row = q >> 2;
            int kq  = (q & 3) * 4;
            const float4 v = *(const float4*)(emb + (size_t)tok_sm[row] * Ee + kt + kq);
            A_sm[kq + 0][row] = v.x;
            A_sm[kq + 1][row] = v.y;
            A_sm[kq + 2][row] = v.z;
            A_sm[kq + 3][row] = v.w;
        }
#pragma unroll
        for (int q = tid; q < (GBK * GBN / 4); q += 256) {
            int k  = q >> 5;
            int c4 = (q & 31) * 4;
            *(float4*)&B_sm[k][c4] = *(const float4*)(W + (size_t)(kt + k) * FOURH + n0 + c4);
        }
        __syncthreads();

#pragma unroll
        for (int k = 0; k < GBK; k++) {
            float a_reg[8];
            *(float4*)&a_reg[0] = *(const float4*)&A_sm[k][tr * 8];
            *(float4*)&a_reg[4] = *(const float4*)&A_sm[k][tr * 8 + 4];
            const ulonglong2 bv0 = *(const ulonglong2*)&B_sm[k][tc * 8];
            const ulonglong2 bv1 = *(const ulonglong2*)&B_sm[k][tc * 8 + 4];
#pragma unroll
            for (int i = 0; i < 8; i++) {
                const u64t ap = pk2(a_reg[i], a_reg[i]);
                FFMA2(acc2[i][0], ap, bv0.x);
                FFMA2(acc2[i][1], ap, bv0.y);
                FFMA2(acc2[i][2], ap, bv1.x);
                FFMA2(acc2[i][3], ap, bv1.y);
            }
        }
        __syncthreads();
    }

    const size_t obase = (size_t)dir * ((size_t)Tt * Bb * FOURH);
#pragma unroll
    for (int i = 0; i < 8; i++) {
        size_t row = (size_t)(m0 + tr * 8 + i);
        float* dst = g_xw + obase + row * FOURH + n0 + tc * 8;
        const float* af = (const float*)&acc2[i][0];
        *(float4*)(dst + 0) = *(const float4*)(af + 0);
        *(float4*)(dst + 4) = *(const float4*)(af + 4);
    }
}

// ---------------------------------------------------------------------------
// Persistent bidirectional LSTM (FFMA2 dot, 4-CTA group barrier).
// Grid 128: dir=bx>>6, btile=(bx&63)>>2 (8 batch rows), utile=bx&3 (32 units).
// 128 threads: jl=tid&31 (unit), bsub=tid>>5 (2 batch rows each).
// ---------------------------------------------------------------------------
__device__ __forceinline__ float sigmoidf_(float x) {
    return 1.0f / (1.0f + __expf(-x));
}

#define LSTM_SMEM (128 * 32 * sizeof(ulonglong2) + 8 * 128 * sizeof(u64t))

__global__ __launch_bounds__(128, 1)
void lstm_kernel(const float* __restrict__ Ufw,
                 const float* __restrict__ Ubw,
                 const float* __restrict__ bfw,
                 const float* __restrict__ bbw,
                 float* __restrict__ out) {
    extern __shared__ char smem_raw[];
    ulonglong2 (*U2)[32] = (ulonglong2(*)[32])smem_raw;                       // [k][jl] 64KB
    u64t (*h2)[128] = (u64t(*)[128])(smem_raw + 128 * 32 * sizeof(ulonglong2)); // [bl][k] 8KB

    const int bx    = blockIdx.x;
    const int dir   = bx >> 6;
    const int id    = bx & 63;
    const int btile = id >> 2;
    const int utile = id & 3;
    const int grp   = (dir * 16 + btile) * 32;   // padded counter index
    const int tid   = threadIdx.x;
    const int jl    = tid & 31;
    const int bsub  = tid >> 5;

    const int j   = utile * 32 + jl;
    const int bl0 = bsub * 2, bl1 = bl0 + 1;
    const int b0  = btile * 8 + bl0, b1 = b0 + 1;

    const float* __restrict__ U    = dir ? Ubw : Ufw;
    const float* __restrict__ bias = dir ? bbw : bfw;

    // U2[k][jl] = { pack(U_i, U_f), pack(U_g, U_o) } for unit j
    for (int k = bsub; k < 128; k += 4) {
        const float* up = U + (size_t)k * FOURH + j;
        ulonglong2 v;
        v.x = pk2(up[0],   up[128]);
        v.y = pk2(up[256], up[384]);
        U2[k][jl] = v;
    }
    const u64t bz01 = pk2(bias[j],            bias[Hh + j]);
    const u64t bz23 = pk2(bias[2 * Hh + j],   bias[3 * Hh + j]);

    float c0 = 0.0f, c1 = 0.0f, hout0 = 0.0f, hout1 = 0.0f;
    const size_t xw_dir = (size_t)dir * ((size_t)Tt * Bb * FOURH);

    for (int t = 0; t < Tt; t++) {
        const int tt = dir ? (Tt - 1 - t) : t;
        const int phase = t & 1;

        // h_prev tile -> smem, duplicated (h,h)
        {
            const float* hp = &g_h[phase][dir][btile * 8][0];
#pragma unroll
            for (int i = tid; i < 8 * 128; i += 128) {
                float v = __ldcg(hp + i);
                ((u64t*)h2)[i] = pk2(v, v);
            }
        }

        // Prefetch xw (consumed after dot)
        const float* xwp = g_xw + xw_dir + ((size_t)tt * Bb) * FOURH;
        const float x00 = __ldg(xwp + (size_t)b0 * FOURH + j);
        const float x01 = __ldg(xwp + (size_t)b0 * FOURH + Hh + j);
        const float x02 = __ldg(xwp + (size_t)b0 * FOURH + 2 * Hh + j);
        const float x03 = __ldg(xwp + (size_t)b0 * FOURH + 3 * Hh + j);
        const float x10 = __ldg(xwp + (size_t)b1 * FOURH + j);
        const float x11 = __ldg(xwp + (size_t)b1 * FOURH + Hh + j);
        const float x12 = __ldg(xwp + (size_t)b1 * FOURH + 2 * Hh + j);
        const float x13 = __ldg(xwp + (size_t)b1 * FOURH + 3 * Hh + j);

        __syncthreads();

        u64t acc01_0 = bz01, acc23_0 = bz23;
        u64t acc01_1 = bz01, acc23_1 = bz23;

#pragma unroll 8
        for (int k = 0; k < 128; k++) {
            const ulonglong2 u = U2[k][jl];
            const u64t h0 = h2[bl0][k];
            const u64t h1 = h2[bl1][k];
            FFMA2(acc01_0, h0, u.x);
            FFMA2(acc23_0, h0, u.y);
            FFMA2(acc01_1, h1, u.x);
            FFMA2(acc23_1, h1, u.y);
        }

        float a00, a01, a02, a03, a10, a11, a12, a13;
        upk2(acc01_0, a00, a01); upk2(acc23_0, a02, a03);
        upk2(acc01_1, a10, a11); upk2(acc23_1, a12, a13);
        a00 += x00; a01 += x01; a02 += x02; a03 += x03;
        a10 += x10; a11 += x11; a12 += x12; a13 += x13;

        {   // gates i,f,g,o
            const float ig = sigmoidf_(a00), fg = sigmoidf_(a01);
            const float gg = tanhf(a02),     og = sigmoidf_(a03);
            c0 = fg * c0 + ig * gg;
            hout0 = og * tanhf(c0);
        }
        {
            const float ig = sigmoidf_(a10), fg = sigmoidf_(a11);
            const float gg = tanhf(a12),     og = sigmoidf_(a13);
            c1 = fg * c1 + ig * gg;
            hout1 = og * tanhf(c1);
        }

        // Publish h (L2)
        __stcg(&g_h[phase ^ 1][dir][b0][j], hout0);
        __stcg(&g_h[phase ^ 1][dir][b1][j], hout1);

        if (t < Tt - 1) {
            __threadfence();
            __syncthreads();
            if (tid == 0) atomicAdd(&g_cnt2[grp], 1u);
            // out stores overlap the barrier wait
            out[((size_t)b0 * Tt + tt) * 256 + dir * Hh + j] = hout0;
            out[((size_t)b1 * Tt + tt) * 256 + dir * Hh + j] = hout1;
            if (tid == 0) {
                const unsigned target = 4u * (unsigned)(t + 1);
                while (*((volatile unsigned*)&g_cnt2[grp]) < target) {}
                __threadfence();
            }
            __syncthreads();
        } else {
            out[((size_t)b0 * Tt + tt) * 256 + dir * Hh + j] = hout0;
            out[((size_t)b1 * Tt + tt) * 256 + dir * Hh + j] = hout1;
        }
    }

    // Final states after [B,T,2H]: h_fw, c_fw, h_bw, c_bw (each [B,H])
    const size_t fin = (size_t)Bb * Tt * 256 + (size_t)dir * 2 * Bb * Hh;
    out[fin + (size_t)b0 * Hh + j]           = hout0;
    out[fin + (size_t)b1 * Hh + j]           = hout1;
    out[fin + Bb * Hh + (size_t)b0 * Hh + j] = c0;
    out[fin + Bb * Hh + (size_t)b1 * Hh + j] = c1;
}

// ---------------------------------------------------------------------------
extern "C" void kernel_launch(void* const* d_in, const int* in_sizes, int n_in,
                              void* d_out, int out_size) {
    const int*   tokens = (const int*)d_in[0];
    const float* emb    = (const float*)d_in[1];
    const float* Wfw    = (const float*)d_in[2];
    const float* Ufw    = (const float*)d_in[3];
    const float* bfw    = (const float*)d_in[4];
    const float* Wbw    = (const float*)d_in[5];
    const float* Ubw    = (const float*)d_in[6];
    const float* bbw    = (const float*)d_in[7];
    float* out = (float*)d_out;

    static bool attr_set = false;
    if (!attr_set) {
        cudaFuncSetAttribute(lstm_kernel,
                             cudaFuncAttributeMaxDynamicSharedMemorySize,
                             (int)LSTM_SMEM);
        attr_set = true;
    }

    reset_kernel<<<64, 256>>>();
    proj_kernel<<<dim3(FOURH / GBN, (Tt * Bb) / GBM, 2), 256>>>(tokens, emb, Wfw, Wbw);
    lstm_kernel<<<128, 128, LSTM_SMEM>>>(Ufw, Ubw, bfw, bbw, out);
}

// round 4
// speedup vs baseline: 1.1074x; 1.0443x over previous
#include <cuda_runtime.h>
#include <math.h>

#define Bb 128
#define Tt 512
#define Ee 256
#define Hh 128
#define FOURH 512

typedef unsigned long long u64t;

__device__ float g_xw[(size_t)2 * Tt * Bb * FOURH];   // [dir][t*128+b][4H]
__device__ float g_h[2][2][Bb][Hh];                   // [phase][dir][b][h]
__device__ unsigned g_cnt2[32 * 32];                  // 32 groups, 128B padded

__device__ __forceinline__ u64t pk2(float lo, float hi) {
    u64t r; asm("mov.b64 %0, {%1, %2};" : "=l"(r) : "f"(lo), "f"(hi)); return r;
}
__device__ __forceinline__ void upk2(u64t v, float& lo, float& hi) {
    asm("mov.b64 {%0, %1}, %2;" : "=f"(lo), "=f"(hi) : "l"(v));
}
#define FFMA2(acc, a, b) asm("fma.rn.f32x2 %0, %1, %2, %0;" : "+l"(acc) : "l"(a), "l"(b))

__device__ __forceinline__ float sigmoid_f(float x) {
    return __fdividef(1.0f, 1.0f + __expf(-x));
}
__device__ __forceinline__ float tanh_f(float x) {
    return __fdividef(2.0f, 1.0f + __expf(-2.0f * x)) - 1.0f;
}

// ---------------------------------------------------------------------------
// Projection GEMM (CTA 0 also zeroes h-state + barrier counters).
// BM=128, BN=128, BK=16, 256 threads, 8x8 microtile, FFMA2 accumulators.
// ---------------------------------------------------------------------------
#define GBM 128
#define GBN 128
#define GBK 16

__global__ __launch_bounds__(256, 2)
void proj_kernel(const int* __restrict__ tokens,
                 const float* __restrict__ emb,
                 const float* __restrict__ Wfw,
                 const float* __restrict__ Wbw) {
    __shared__ __align__(16) float A_sm[GBK][GBM + 4];
    __shared__ __align__(16) float B_sm[GBK][GBN];
    __shared__ int tok_sm[GBM];

    const int tid = threadIdx.x;

    // Fold reset into the GEMM launch (runs before lstm by stream order)
    if (blockIdx.x == 0 && blockIdx.y == 0 && blockIdx.z == 0) {
        float* hp = &g_h[0][0][0][0];
        for (int i = tid; i < 2 * 2 * Bb * Hh; i += 256) hp[i] = 0.0f;
        for (int i = tid; i < 32 * 32; i += 256) g_cnt2[i] = 0u;
    }

    const int dir = blockIdx.z;
    const float* __restrict__ W = dir ? Wbw : Wfw;
    const int n0 = blockIdx.x * GBN;
    const int m0 = blockIdx.y * GBM;

    if (tid < GBM) {
        int row = m0 + tid;
        tok_sm[tid] = tokens[(row & 127) * Tt + (row >> 7)];
    }
    __syncthreads();

    const int tr = tid >> 4;
    const int tc = tid & 15;

    __align__(16) u64t acc2[8][4];
#pragma unroll
    for (int i = 0; i < 8; i++)
#pragma unroll
        for (int j = 0; j < 4; j++) acc2[i][j] = 0ull;

    for (int kt = 0; kt < Ee; kt += GBK) {
#pragma unroll
        for (int q = tid; q < (GBM * GBK / 4); q += 256) {
            int row = q >> 2;
            int kq  = (q & 3) * 4;
            const float4 v = *(const float4*)(emb + (size_t)tok_sm[row] * Ee + kt + kq);
            A_sm[kq + 0][row] = v.x;
            A_sm[kq + 1][row] = v.y;
            A_sm[kq + 2][row] = v.z;
            A_sm[kq + 3][row] = v.w;
        }
#pragma unroll
        for (int q = tid; q < (GBK * GBN / 4); q += 256) {
            int k  = q >> 5;
            int c4 = (q & 31) * 4;
            *(float4*)&B_sm[k][c4] = *(const float4*)(W + (size_t)(kt + k) * FOURH + n0 + c4);
        }
        __syncthreads();

#pragma unroll
        for (int k = 0; k < GBK; k++) {
            float a_reg[8];
            *(float4*)&a_reg[0] = *(const float4*)&A_sm[k][tr * 8];
            *(float4*)&a_reg[4] = *(const float4*)&A_sm[k][tr * 8 + 4];
            const ulonglong2 bv0 = *(const ulonglong2*)&B_sm[k][tc * 8];
            const ulonglong2 bv1 = *(const ulonglong2*)&B_sm[k][tc * 8 + 4];
#pragma unroll
            for (int i = 0; i < 8; i++) {
                const u64t ap = pk2(a_reg[i], a_reg[i]);
                FFMA2(acc2[i][0], ap, bv0.x);
                FFMA2(acc2[i][1], ap, bv0.y);
                FFMA2(acc2[i][2], ap, bv1.x);
                FFMA2(acc2[i][3], ap, bv1.y);
            }
        }
        __syncthreads();
    }

    const size_t obase = (size_t)dir * ((size_t)Tt * Bb * FOURH);
#pragma unroll
    for (int i = 0; i < 8; i++) {
        size_t row = (size_t)(m0 + tr * 8 + i);
        float* dst = g_xw + obase + row * FOURH + n0 + tc * 8;
        const float* af = (const float*)&acc2[i][0];
        *(float4*)(dst + 0) = *(const float4*)(af + 0);
        *(float4*)(dst + 4) = *(const float4*)(af + 4);
    }
}

// ---------------------------------------------------------------------------
// Persistent bidirectional LSTM.
// Grid 128: dir=bx>>6, btile=(bx&63)>>2 (8 batch rows), utile=bx&3 (32 units).
// Warp w owns units [w*8, w*8+8); lane = (ul = lane>>2, bpair = lane&3).
// Each lane: 1 unit x 2 batch rows, all 4 gates as two f32x2 accumulators.
// Warps read DISJOINT 128B U slices per k (no cross-warp crossbar duplication).
// ---------------------------------------------------------------------------
#define HPAD 10   // h2t row stride in u64t (80B: 16B aligned, low STS conflict)
#define LSTM_SMEM (128 * 32 * sizeof(ulonglong2) + 128 * HPAD * sizeof(u64t))

__global__ __launch_bounds__(128, 1)
void lstm_kernel(const float* __restrict__ Ufw,
                 const float* __restrict__ Ubw,
                 const float* __restrict__ bfw,
                 const float* __restrict__ bbw,
                 float* __restrict__ out) {
    extern __shared__ char smem_raw[];
    ulonglong2 (*U2)[32] = (ulonglong2(*)[32])smem_raw;                        // [k][unit_local]
    u64t (*h2t)[HPAD] = (u64t(*)[HPAD])(smem_raw + 128 * 32 * sizeof(ulonglong2)); // [k][bl] dup pairs

    const int bx    = blockIdx.x;
    const int dir   = bx >> 6;
    const int id    = bx & 63;
    const int btile = id >> 2;
    const int utile = id & 3;
    const int grp   = (dir * 16 + btile) * 32;
    const int tid   = threadIdx.x;
    const int wid   = tid >> 5;
    const int lane  = tid & 31;
    const int ul    = lane >> 2;          // unit within warp's 8
    const int bpair = lane & 3;           // batch pair

    const int ju  = wid * 8 + ul;         // unit local 0..31
    const int j   = utile * 32 + ju;      // global unit
    const int bl0 = bpair * 2, bl1 = bl0 + 1;
    const int b0  = btile * 8 + bl0, b1 = b0 + 1;

    const float* __restrict__ U    = dir ? Ubw : Ufw;
    const float* __restrict__ bias = dir ? bbw : bfw;

    // U2[k][m]: gate pairs for unit (utile*32+m): {pk(Ui,Uf), pk(Ug,Uo)}
    {
        const int jl_ld = tid & 31;
        const int jg = utile * 32 + jl_ld;
        for (int k = wid; k < 128; k += 4) {
            const float* up = U + (size_t)k * FOURH + jg;
            ulonglong2 v;
            v.x = pk2(up[0],   up[128]);
            v.y = pk2(up[256], up[384]);
            U2[k][jl_ld] = v;
        }
    }
    const u64t bz01 = pk2(bias[j],          bias[Hh + j]);
    const u64t bz23 = pk2(bias[2 * Hh + j], bias[3 * Hh + j]);

    float c0 = 0.0f, c1 = 0.0f, hout0 = 0.0f, hout1 = 0.0f;
    const size_t xw_dir = (size_t)dir * ((size_t)Tt * Bb * FOURH);

    for (int t = 0; t < Tt; t++) {
        const int tt = dir ? (Tt - 1 - t) : t;
        const int phase = t & 1;

        // h_prev [8 x 128] -> h2t[k][bl] duplicated pairs
        {
            const float* hp = &g_h[phase][dir][btile * 8][0];
#pragma unroll
            for (int q = tid; q < 8 * 128; q += 128) {
                float v = __ldcg(hp + q);          // coalesced [bl][k]
                h2t[q & 127][q >> 7] = pk2(v, v);  // transposed store
            }
        }

        const float* xwp = g_xw + xw_dir + ((size_t)tt * Bb) * FOURH;
        const float x00 = __ldg(xwp + (size_t)b0 * FOURH + j);
        const float x01 = __ldg(xwp + (size_t)b0 * FOURH + Hh + j);
        const float x02 = __ldg(xwp + (size_t)b0 * FOURH + 2 * Hh + j);
        const float x03 = __ldg(xwp + (size_t)b0 * FOURH + 3 * Hh + j);
        const float x10 = __ldg(xwp + (size_t)b1 * FOURH + j);
        const float x11 = __ldg(xwp + (size_t)b1 * FOURH + Hh + j);
        const float x12 = __ldg(xwp + (size_t)b1 * FOURH + 2 * Hh + j);
        const float x13 = __ldg(xwp + (size_t)b1 * FOURH + 3 * Hh + j);

        __syncthreads();

        u64t acc01_0 = bz01, acc23_0 = bz23;
        u64t acc01_1 = bz01, acc23_1 = bz23;

#pragma unroll 16
        for (int k = 0; k < 128; k++) {
            const ulonglong2 u  = U2[k][ju];
            const ulonglong2 hh = *(const ulonglong2*)&h2t[k][bl0];
            FFMA2(acc01_0, hh.x, u.x);
            FFMA2(acc23_0, hh.x, u.y);
            FFMA2(acc01_1, hh.y, u.x);
            FFMA2(acc23_1, hh.y, u.y);
        }

        float a00, a01, a02, a03, a10, a11, a12, a13;
        upk2(acc01_0, a00, a01); upk2(acc23_0, a02, a03);
        upk2(acc01_1, a10, a11); upk2(acc23_1, a12, a13);
        a00 += x00; a01 += x01; a02 += x02; a03 += x03;
        a10 += x10; a11 += x11; a12 += x12; a13 += x13;

        {
            const float ig = sigmoid_f(a00), fg = sigmoid_f(a01);
            const float gg = tanh_f(a02),    og = sigmoid_f(a03);
            c0 = fg * c0 + ig * gg;
            hout0 = og * tanh_f(c0);
        }
        {
            const float ig = sigmoid_f(a10), fg = sigmoid_f(a11);
            const float gg = tanh_f(a12),    og = sigmoid_f(a13);
            c1 = fg * c1 + ig * gg;
            hout1 = og * tanh_f(c1);
        }

        __stcg(&g_h[phase ^ 1][dir][b0][j], hout0);
        __stcg(&g_h[phase ^ 1][dir][b1][j], hout1);

        out[((size_t)b0 * Tt + tt) * 256 + dir * Hh + j] = hout0;
        out[((size_t)b1 * Tt + tt) * 256 + dir * Hh + j] = hout1;

        if (t < Tt - 1) {
            __threadfence();
            __syncthreads();
            if (tid == 0) {
                atomicAdd(&g_cnt2[grp], 1u);
                const unsigned target = 4u * (unsigned)(t + 1);
                while (*((volatile unsigned*)&g_cnt2[grp]) < target) {}
                __threadfence();
            }
            __syncthreads();
        }
    }

    const size_t fin = (size_t)Bb * Tt * 256 + (size_t)dir * 2 * Bb * Hh;
    out[fin + (size_t)b0 * Hh + j]           = hout0;
    out[fin + (size_t)b1 * Hh + j]           = hout1;
    out[fin + Bb * Hh + (size_t)b0 * Hh + j] = c0;
    out[fin + Bb * Hh + (size_t)b1 * Hh + j] = c1;
}

// ---------------------------------------------------------------------------
extern "C" void kernel_launch(void* const* d_in, const int* in_sizes, int n_in,
                              void* d_out, int out_size) {
    const int*   tokens = (const int*)d_in[0];
    const float* emb    = (const float*)d_in[1];
    const float* Wfw    = (const float*)d_in[2];
    const float* Ufw    = (const float*)d_in[3];
    const float* bfw    = (const float*)d_in[4];
    const float* Wbw    = (const float*)d_in[5];
    const float* Ubw    = (const float*)d_in[6];
    const float* bbw    = (const float*)d_in[7];
    float* out = (float*)d_out;

    static bool attr_set = false;
    if (!attr_set) {
        cudaFuncSetAttribute(lstm_kernel,
                             cudaFuncAttributeMaxDynamicSharedMemorySize,
                             (int)LSTM_SMEM);
        attr_set = true;
    }

    proj_kernel<<<dim3(FOURH / GBN, (Tt * Bb) / GBM, 2), 256>>>(tokens, emb, Wfw, Wbw);
    lstm_kernel<<<128, 128, LSTM_SMEM>>>(Ufw, Ubw, bfw, bbw, out);
}

// round 6
// speedup vs baseline: 1.2561x; 1.1342x over previous
#include <cuda_runtime.h>
#include <cuda_bf16.h>
#include <cstdint>
#include <math.h>

#define Bb 128
#define Tt 512
#define Ee 256
#define Hh 128
#define FOURH 512
#define Vv 32000
#define KP 768

typedef unsigned long long u64t;
typedef __nv_bfloat16 bf16;

// ---------------- static scratch ----------------
__device__ float g_xw[(size_t)2 * Tt * Bb * FOURH];      // [dir][t*128+b][4H]
__device__ float g_h[2][2][Bb][Hh];
__device__ unsigned g_cnt2[32 * 32];
__device__ __align__(16) bf16 g_ehi[(size_t)Vv * Ee];
__device__ __align__(16) bf16 g_elo[(size_t)Vv * Ee];
__device__ __align__(16) bf16 g_Wt[2][KP][FOURH];        // [dir][k'][n]

// ---------------- helpers ----------------
__device__ __forceinline__ u64t pk2(float lo, float hi) {
    u64t r; asm("mov.b64 %0, {%1, %2};" : "=l"(r) : "f"(lo), "f"(hi)); return r;
}
__device__ __forceinline__ void upk2(u64t v, float& lo, float& hi) {
    asm("mov.b64 {%0, %1}, %2;" : "=f"(lo), "=f"(hi) : "l"(v));
}
#define FFMA2(acc, a, b) asm("fma.rn.f32x2 %0, %1, %2, %0;" : "+l"(acc) : "l"(a), "l"(b))
__device__ __forceinline__ float sigmoid_f(float x) { return __fdividef(1.0f, 1.0f + __expf(-x)); }
__device__ __forceinline__ float tanh_f(float x)    { return __fdividef(2.0f, 1.0f + __expf(-2.0f * x)) - 1.0f; }
__device__ __forceinline__ uint32_t smem_u32(const void* p) {
    uint32_t a;
    asm("{ .reg .u64 t; cvta.to.shared.u64 t, %1; cvt.u32.u64 %0, t; }" : "=r"(a) : "l"(p));
    return a;
}
#define LDSM_X4(r0, r1, r2, r3, addr) \
    asm volatile("ldmatrix.sync.aligned.m8n8.x4.shared.b16 {%0,%1,%2,%3}, [%4];" \
                 : "=r"(r0), "=r"(r1), "=r"(r2), "=r"(r3) : "r"(addr))
#define LDSM_X4T(r0, r1, r2, r3, addr) \
    asm volatile("ldmatrix.sync.aligned.m8n8.x4.trans.shared.b16 {%0,%1,%2,%3}, [%4];" \
                 : "=r"(r0), "=r"(r1), "=r"(r2), "=r"(r3) : "r"(addr))
#define MMA16816(c, a, b0, b1) \
    asm volatile("mma.sync.aligned.m16n8k16.row.col.f32.bf16.bf16.f32 " \
                 "{%0,%1,%2,%3}, {%4,%5,%6,%7}, {%8,%9}, {%0,%1,%2,%3};" \
                 : "+f"((c)[0]), "+f"((c)[1]), "+f"((c)[2]), "+f"((c)[3]) \
                 : "r"((a)[0]), "r"((a)[1]), "r"((a)[2]), "r"((a)[3]), "r"(b0), "r"(b1))

// ---------------- conversion kernels ----------------
__global__ void conv_emb(const float* __restrict__ emb) {
    size_t i = (size_t)blockIdx.x * 256 + threadIdx.x;
    if (i < (size_t)Vv * Ee) {
        float x = emb[i];
        bf16 h = __float2bfloat16(x);
        g_ehi[i] = h;
        g_elo[i] = __float2bfloat16(x - __bfloat162float(h));
    }
}
// g_Wt[d][kp][n]: kp<256 hi(W[kp][n]); 256..511 lo(W[kp-256][n]); 512..767 hi(W[kp-512][n])
__global__ void conv_w(const float* __restrict__ Wfw, const float* __restrict__ Wbw) {
    if (blockIdx.x == 0) {
        float* hp = &g_h[0][0][0][0];
        for (int q = threadIdx.x; q < 2 * 2 * Bb * Hh; q += 256) hp[q] = 0.0f;
        for (int q = threadIdx.x; q < 32 * 32; q += 256) g_cnt2[q] = 0u;
    }
    int i = blockIdx.x * 256 + threadIdx.x;
    if (i < 2 * KP * FOURH) {
        int d  = i / (KP * FOURH);
        int r  = i % (KP * FOURH);
        int kp = r / FOURH, n = r % FOURH;
        const float* W = d ? Wbw : Wfw;
        float x = W[(size_t)(kp & 255) * FOURH + n];
        bf16 hv = __float2bfloat16(x);
        g_Wt[d][kp][n] = (kp >= 256 && kp < 512)
                             ? __float2bfloat16(x - __bfloat162float(hv)) : hv;
    }
}

// ---------------- mma.sync projection GEMM ----------------
// CTA 128M x 128N, K'=768 in 24 chunks of 32. 8 warps = 4(m) x 2(n),
// warp tile 32x64. A_sm stride 40 bf16 (80B), B_sm stride 136 bf16 (272B).
#define ASTR 40
#define BSTR 136

__global__ __launch_bounds__(256)
void proj_mma(const int* __restrict__ tokens) {
    __shared__ __align__(16) bf16 A_sm[128 * ASTR];
    __shared__ __align__(16) bf16 B_sm[32 * BSTR];
    __shared__ int tok[128];

    const int tid = threadIdx.x;
    const int wid = tid >> 5, lane = tid & 31;
    const int wm = wid & 3, wn = wid >> 2;
    const int n0 = blockIdx.x * 128;
    const int m0 = blockIdx.y * 128;
    const int dir = blockIdx.z;

    if (tid < 128) {
        int row = m0 + tid;
        tok[tid] = tokens[(row & 127) * Tt + (row >> 7)];
    }

    const uint32_t sbA = smem_u32(A_sm);
    const uint32_t sbB = smem_u32(B_sm);

    float c[2][8][4];
#pragma unroll
    for (int i = 0; i < 2; i++)
#pragma unroll
        for (int j = 0; j < 8; j++)
#pragma unroll
            for (int q = 0; q < 4; q++) c[i][j][q] = 0.0f;

    // first-iteration token dependency
    __syncthreads();

    for (int kt = 0; kt < 24; kt++) {
        const int kp0 = kt * 32;
        const bf16* __restrict__ Asrc = (kp0 < 512) ? g_ehi : g_elo;
        const int kb = kp0 & 255;

        uint4 av[2], bv[2];
#pragma unroll
        for (int u = 0; u < 2; u++) {
            const int q = tid + u * 256;           // 0..511
            const int arow = q >> 2, ac8 = q & 3;
            av[u] = *(const uint4*)(Asrc + (size_t)tok[arow] * Ee + kb + ac8 * 8);
            const int brow = q >> 4, bn8 = q & 15;
            bv[u] = *(const uint4*)(&g_Wt[dir][kp0 + brow][n0 + bn8 * 8]);
        }
        __syncthreads();   // previous compute done before overwriting smem
#pragma unroll
        for (int u = 0; u < 2; u++) {
            const int q = tid + u * 256;
            const int arow = q >> 2, ac8 = q & 3;
            *(uint4*)(A_sm + arow * ASTR + ac8 * 8) = av[u];
            const int brow = q >> 4, bn8 = q & 15;
            *(uint4*)(B_sm + brow * BSTR + bn8 * 8) = bv[u];
        }
        __syncthreads();

#pragma unroll
        for (int ks = 0; ks < 2; ks++) {
            uint32_t a[2][4];
#pragma unroll
            for (int i = 0; i < 2; i++) {
                const int m = wm * 32 + i * 16 + (lane & 7) + ((lane >> 3) & 1) * 8;
                const int kc = ks * 16 + (lane >> 4) * 8;
                LDSM_X4(a[i][0], a[i][1], a[i][2], a[i][3],
                        sbA + (uint32_t)(m * ASTR + kc) * 2);
            }
            uint32_t b[4][4];
#pragma unroll
            for (int j2 = 0; j2 < 4; j2++) {
                const int k = ks * 16 + (lane & 7) + ((lane >> 3) & 1) * 8;
                const int n = wn * 64 + j2 * 16 + (lane >> 4) * 8;
                LDSM_X4T(b[j2][0], b[j2][1], b[j2][2], b[j2][3],
                         sbB + (uint32_t)(k * BSTR + n) * 2);
            }
#pragma unroll
            for (int i = 0; i < 2; i++)
#pragma unroll
                for (int j = 0; j < 8; j++)
                    MMA16816(c[i][j], a[i], b[j >> 1][(j & 1) * 2], b[j >> 1][(j & 1) * 2 + 1]);
        }
    }

    // epilogue: C frags -> g_xw
    const int g = lane >> 2, t2 = (lane & 3) * 2;
    float* const base = g_xw + (size_t)dir * Tt * Bb * FOURH;
#pragma unroll
    for (int i = 0; i < 2; i++) {
        const int mrow = m0 + wm * 32 + i * 16 + g;
#pragma unroll
        for (int j = 0; j < 8; j++) {
            const int col = n0 + wn * 64 + j * 8 + t2;
            float* d0 = base + (size_t)mrow * FOURH + col;
            d0[0] = c[i][j][0]; d0[1] = c[i][j][1];
            float* d1 = d0 + 8 * FOURH;
            d1[0] = c[i][j][2]; d1[1] = c[i][j][3];
        }
    }
}

// ---------------- persistent LSTM (unchanged from R4) ----------------
#define HPAD 10
#define LSTM_SMEM (128 * 32 * sizeof(ulonglong2) + 128 * HPAD * sizeof(u64t))

__global__ __launch_bounds__(128, 1)
void lstm_kernel(const float* __restrict__ Ufw, const float* __restrict__ Ubw,
                 const float* __restrict__ bfw, const float* __restrict__ bbw,
                 float* __restrict__ out) {
    extern __shared__ char smem_raw[];
    ulonglong2 (*U2)[32] = (ulonglong2(*)[32])smem_raw;
    u64t (*h2t)[HPAD] = (u64t(*)[HPAD])(smem_raw + 128 * 32 * sizeof(ulonglong2));

    const int bx = blockIdx.x;
    const int dir = bx >> 6, id = bx & 63;
    const int btile = id >> 2, utile = id & 3;
    const int grp = (dir * 16 + btile) * 32;
    const int tid = threadIdx.x, wid = tid >> 5, lane = tid & 31;
    const int ul = lane >> 2, bpair = lane & 3;
    const int ju = wid * 8 + ul;
    const int j = utile * 32 + ju;
    const int bl0 = bpair * 2;
    const int b0 = btile * 8 + bl0, b1 = b0 + 1;

    const float* __restrict__ U    = dir ? Ubw : Ufw;
    const float* __restrict__ bias = dir ? bbw : bfw;

    {
        const int jl_ld = tid & 31;
        const int jg = utile * 32 + jl_ld;
        for (int k = wid; k < 128; k += 4) {
            const float* up = U + (size_t)k * FOURH + jg;
            ulonglong2 v;
            v.x = pk2(up[0], up[128]);
            v.y = pk2(up[256], up[384]);
            U2[k][jl_ld] = v;
        }
    }
    const u64t bz01 = pk2(bias[j], bias[Hh + j]);
    const u64t bz23 = pk2(bias[2 * Hh + j], bias[3 * Hh + j]);

    float c0 = 0.0f, c1 = 0.0f, hout0 = 0.0f, hout1 = 0.0f;
    const size_t xw_dir = (size_t)dir * ((size_t)Tt * Bb * FOURH);

    for (int t = 0; t < Tt; t++) {
        const int tt = dir ? (Tt - 1 - t) : t;
        const int phase = t & 1;
        {
            const float* hp = &g_h[phase][dir][btile * 8][0];
#pragma unroll
            for (int q = tid; q < 8 * 128; q += 128) {
                float v = __ldcg(hp + q);
                h2t[q & 127][q >> 7] = pk2(v, v);
            }
        }
        const float* xwp = g_xw + xw_dir + ((size_t)tt * Bb) * FOURH;
        const float x00 = __ldg(xwp + (size_t)b0 * FOURH + j);
        const float x01 = __ldg(xwp + (size_t)b0 * FOURH + Hh + j);
        const float x02 = __ldg(xwp + (size_t)b0 * FOURH + 2 * Hh + j);
        const float x03 = __ldg(xwp + (size_t)b0 * FOURH + 3 * Hh + j);
        const float x10 = __ldg(xwp + (size_t)b1 * FOURH + j);
        const float x11 = __ldg(xwp + (size_t)b1 * FOURH + Hh + j);
        const float x12 = __ldg(xwp + (size_t)b1 * FOURH + 2 * Hh + j);
        const float x13 = __ldg(xwp + (size_t)b1 * FOURH + 3 * Hh + j);

        __syncthreads();

        u64t acc01_0 = bz01, acc23_0 = bz23;
        u64t acc01_1 = bz01, acc23_1 = bz23;
#pragma unroll 16
        for (int k = 0; k < 128; k++) {
            const ulonglong2 u = U2[k][ju];
            const ulonglong2 hh = *(const ulonglong2*)&h2t[k][bl0];
            FFMA2(acc01_0, hh.x, u.x);
            FFMA2(acc23_0, hh.x, u.y);
            FFMA2(acc01_1, hh.y, u.x);
            FFMA2(acc23_1, hh.y, u.y);
        }
        float a00, a01, a02, a03, a10, a11, a12, a13;
        upk2(acc01_0, a00, a01); upk2(acc23_0, a02, a03);
        upk2(acc01_1, a10, a11); upk2(acc23_1, a12, a13);
        a00 += x00; a01 += x01; a02 += x02; a03 += x03;
        a10 += x10; a11 += x11; a12 += x12; a13 += x13;
        {
            const float ig = sigmoid_f(a00), fg = sigmoid_f(a01);
            const float gg = tanh_f(a02), og = sigmoid_f(a03);
            c0 = fg * c0 + ig * gg;
            hout0 = og * tanh_f(c0);
        }
        {
            const float ig = sigmoid_f(a10), fg = sigmoid_f(a11);
            const float gg = tanh_f(a12), og = sigmoid_f(a13);
            c1 = fg * c1 + ig * gg;
            hout1 = og * tanh_f(c1);
        }
        __stcg(&g_h[phase ^ 1][dir][b0][j], hout0);
        __stcg(&g_h[phase ^ 1][dir][b1][j], hout1);
        out[((size_t)b0 * Tt + tt) * 256 + dir * Hh + j] = hout0;
        out[((size_t)b1 * Tt + tt) * 256 + dir * Hh + j] = hout1;

        if (t < Tt - 1) {
            __threadfence();
            __syncthreads();
            if (tid == 0) {
                atomicAdd(&g_cnt2[grp], 1u);
                const unsigned target = 4u * (unsigned)(t + 1);
                while (*((volatile unsigned*)&g_cnt2[grp]) < target) {}
                __threadfence();
            }
            __syncthreads();
        }
    }
    const size_t fin = (size_t)Bb * Tt * 256 + (size_t)dir * 2 * Bb * Hh;
    out[fin + (size_t)b0 * Hh + j] = hout0;
    out[fin + (size_t)b1 * Hh + j] = hout1;
    out[fin + Bb * Hh + (size_t)b0 * Hh + j] = c0;
    out[fin + Bb * Hh + (size_t)b1 * Hh + j] = c1;
}

// ---------------- launch ----------------
extern "C" void kernel_launch(void* const* d_in, const int* in_sizes, int n_in,
                              void* d_out, int out_size) {
    const int*   tokens = (const int*)d_in[0];
    const float* emb    = (const float*)d_in[1];
    const float* Ufw    = (const float*)d_in[3];
    const float* bfw    = (const float*)d_in[4];
    const float* Ubw    = (const float*)d_in[6];
    const float* bbw    = (const float*)d_in[7];
    const float* Wfw    = (const float*)d_in[2];
    const float* Wbw    = (const float*)d_in[5];
    float* out = (float*)d_out;

    static bool attr_set = false;
    if (!attr_set) {
        cudaFuncSetAttribute(lstm_kernel, cudaFuncAttributeMaxDynamicSharedMemorySize, (int)LSTM_SMEM);
        attr_set = true;
    }

    conv_emb<<<(Vv * Ee + 255) / 256, 256>>>(emb);
    conv_w<<<(2 * KP * FOURH + 255) / 256, 256>>>(Wfw, Wbw);
    proj_mma<<<dim3(4, 512, 2), 256>>>(tokens);
    lstm_kernel<<<128, 128, LSTM_SMEM>>>(Ufw, Ubw, bfw, bbw, out);
}

// round 7
// speedup vs baseline: 1.5428x; 1.2283x over previous
#include <cuda_runtime.h>
#include <cuda_bf16.h>
#include <cstdint>
#include <math.h>

#define Bb 128
#define Tt 512
#define Ee 256
#define Hh 128
#define FOURH 512
#define Vv 32000
#define KP 768

typedef unsigned long long u64t;
typedef __nv_bfloat16 bf16;

// ---------------- static scratch ----------------
__device__ float g_xw[(size_t)2 * Tt * Bb * FOURH];      // [dir][t*128+b][4H]
__device__ __align__(16) bf16 g_ehi[(size_t)Vv * Ee];
__device__ __align__(16) bf16 g_elo[(size_t)Vv * Ee];
__device__ __align__(16) bf16 g_Wt[2][KP][FOURH];        // [dir][k'][n]

// ---------------- helpers ----------------
__device__ __forceinline__ u64t pk2(float lo, float hi) {
    u64t r; asm("mov.b64 %0, {%1, %2};" : "=l"(r) : "f"(lo), "f"(hi)); return r;
}
__device__ __forceinline__ void upk2(u64t v, float& lo, float& hi) {
    asm("mov.b64 {%0, %1}, %2;" : "=f"(lo), "=f"(hi) : "l"(v));
}
#define FFMA2(acc, a, b) asm("fma.rn.f32x2 %0, %1, %2, %0;" : "+l"(acc) : "l"(a), "l"(b))
__device__ __forceinline__ float sigmoid_f(float x) { return __fdividef(1.0f, 1.0f + __expf(-x)); }
__device__ __forceinline__ float tanh_f(float x)    { return __fdividef(2.0f, 1.0f + __expf(-2.0f * x)) - 1.0f; }
__device__ __forceinline__ uint32_t smem_u32(const void* p) {
    uint32_t a;
    asm("{ .reg .u64 t; cvta.to.shared.u64 t, %1; cvt.u32.u64 %0, t; }" : "=r"(a) : "l"(p));
    return a;
}
// DSMEM store of u64 into cluster CTA `rank` at same smem offset
__device__ __forceinline__ void st_cluster_u64(uint32_t laddr, int rank, u64t v) {
    asm volatile(
        "{ .reg .b32 ra; mapa.shared::cluster.u32 ra, %0, %1; "
        "st.shared::cluster.b64 [ra], %2; }"
        :: "r"(laddr), "r"(rank), "l"(v) : "memory");
}
#define CLUSTER_SYNC() do { \
    asm volatile("barrier.cluster.arrive.aligned;" ::: "memory"); \
    asm volatile("barrier.cluster.wait.aligned;" ::: "memory"); \
} while (0)

#define LDSM_X4(r0, r1, r2, r3, addr) \
    asm volatile("ldmatrix.sync.aligned.m8n8.x4.shared.b16 {%0,%1,%2,%3}, [%4];" \
                 : "=r"(r0), "=r"(r1), "=r"(r2), "=r"(r3) : "r"(addr))
#define LDSM_X4T(r0, r1, r2, r3, addr) \
    asm volatile("ldmatrix.sync.aligned.m8n8.x4.trans.shared.b16 {%0,%1,%2,%3}, [%4];" \
                 : "=r"(r0), "=r"(r1), "=r"(r2), "=r"(r3) : "r"(addr))
#define MMA16816(c, a, b0, b1) \
    asm volatile("mma.sync.aligned.m16n8k16.row.col.f32.bf16.bf16.f32 " \
                 "{%0,%1,%2,%3}, {%4,%5,%6,%7}, {%8,%9}, {%0,%1,%2,%3};" \
                 : "+f"((c)[0]), "+f"((c)[1]), "+f"((c)[2]), "+f"((c)[3]) \
                 : "r"((a)[0]), "r"((a)[1]), "r"((a)[2]), "r"((a)[3]), "r"(b0), "r"(b1))

// ---------------- conversion kernels ----------------
__global__ void conv_emb(const float* __restrict__ emb) {
    size_t i = (size_t)blockIdx.x * 256 + threadIdx.x;
    if (i < (size_t)Vv * Ee) {
        float x = emb[i];
        bf16 h = __float2bfloat16(x);
        g_ehi[i] = h;
        g_elo[i] = __float2bfloat16(x - __bfloat162float(h));
    }
}
__global__ void conv_w(const float* __restrict__ Wfw, const float* __restrict__ Wbw) {
    int i = blockIdx.x * 256 + threadIdx.x;
    if (i < 2 * KP * FOURH) {
        int d  = i / (KP * FOURH);
        int r  = i % (KP * FOURH);
        int kp = r / FOURH, n = r % FOURH;
        const float* W = d ? Wbw : Wfw;
        float x = W[(size_t)(kp & 255) * FOURH + n];
        bf16 hv = __float2bfloat16(x);
        g_Wt[d][kp][n] = (kp >= 256 && kp < 512)
                             ? __float2bfloat16(x - __bfloat162float(hv)) : hv;
    }
}

// ---------------- mma.sync projection GEMM (unchanged from R6) ----------------
#define ASTR 40
#define BSTR 136

__global__ __launch_bounds__(256)
void proj_mma(const int* __restrict__ tokens) {
    __shared__ __align__(16) bf16 A_sm[128 * ASTR];
    __shared__ __align__(16) bf16 B_sm[32 * BSTR];
    __shared__ int tok[128];

    const int tid = threadIdx.x;
    const int wid = tid >> 5, lane = tid & 31;
    const int wm = wid & 3, wn = wid >> 2;
    const int n0 = blockIdx.x * 128;
    const int m0 = blockIdx.y * 128;
    const int dir = blockIdx.z;

    if (tid < 128) {
        int row = m0 + tid;
        tok[tid] = tokens[(row & 127) * Tt + (row >> 7)];
    }
    const uint32_t sbA = smem_u32(A_sm);
    const uint32_t sbB = smem_u32(B_sm);

    float c[2][8][4];
#pragma unroll
    for (int i = 0; i < 2; i++)
#pragma unroll
        for (int j = 0; j < 8; j++)
#pragma unroll
            for (int q = 0; q < 4; q++) c[i][j][q] = 0.0f;

    __syncthreads();

    for (int kt = 0; kt < 24; kt++) {
        const int kp0 = kt * 32;
        const bf16* __restrict__ Asrc = (kp0 < 512) ? g_ehi : g_elo;
        const int kb = kp0 & 255;

        uint4 av[2], bv[2];
#pragma unroll
        for (int u = 0; u < 2; u++) {
            const int q = tid + u * 256;
            const int arow = q >> 2, ac8 = q & 3;
            av[u] = *(const uint4*)(Asrc + (size_t)tok[arow] * Ee + kb + ac8 * 8);
            const int brow = q >> 4, bn8 = q & 15;
            bv[u] = *(const uint4*)(&g_Wt[dir][kp0 + brow][n0 + bn8 * 8]);
        }
        __syncthreads();
#pragma unroll
        for (int u = 0; u < 2; u++) {
            const int q = tid + u * 256;
            const int arow = q >> 2, ac8 = q & 3;
            *(uint4*)(A_sm + arow * ASTR + ac8 * 8) = av[u];
            const int brow = q >> 4, bn8 = q & 15;
            *(uint4*)(B_sm + brow * BSTR + bn8 * 8) = bv[u];
        }
        __syncthreads();

#pragma unroll
        for (int ks = 0; ks < 2; ks++) {
            uint32_t a[2][4];
#pragma unroll
            for (int i = 0; i < 2; i++) {
                const int m = wm * 32 + i * 16 + (lane & 7) + ((lane >> 3) & 1) * 8;
                const int kc = ks * 16 + (lane >> 4) * 8;
                LDSM_X4(a[i][0], a[i][1], a[i][2], a[i][3],
                        sbA + (uint32_t)(m * ASTR + kc) * 2);
            }
            uint32_t b[4][4];
#pragma unroll
            for (int j2 = 0; j2 < 4; j2++) {
                const int k = ks * 16 + (lane & 7) + ((lane >> 3) & 1) * 8;
                const int n = wn * 64 + j2 * 16 + (lane >> 4) * 8;
                LDSM_X4T(b[j2][0], b[j2][1], b[j2][2], b[j2][3],
                         sbB + (uint32_t)(k * BSTR + n) * 2);
            }
#pragma unroll
            for (int i = 0; i < 2; i++)
#pragma unroll
                for (int j = 0; j < 8; j++)
                    MMA16816(c[i][j], a[i], b[j >> 1][(j & 1) * 2], b[j >> 1][(j & 1) * 2 + 1]);
        }
    }

    const int g = lane >> 2, t2 = (lane & 3) * 2;
    float* const base = g_xw + (size_t)dir * Tt * Bb * FOURH;
#pragma unroll
    for (int i = 0; i < 2; i++) {
        const int mrow = m0 + wm * 32 + i * 16 + g;
#pragma unroll
        for (int j = 0; j < 8; j++) {
            const int col = n0 + wn * 64 + j * 8 + t2;
            float* d0 = base + (size_t)mrow * FOURH + col;
            d0[0] = c[i][j][0]; d0[1] = c[i][j][1];
            float* d1 = d0 + 8 * FOURH;
            d1[0] = c[i][j][2]; d1[1] = c[i][j][3];
        }
    }
}

// ---------------- persistent LSTM: cluster(4) + DSMEM h-exchange ----------------
// 128 CTAs, cluster = 4 consecutive = one (dir,btile). CTA handles 32 units
// (utile) x 8 batch rows. h double-buffered in smem, peers write via DSMEM.
#define HPAD 10
#define U2_BYTES (128 * 32 * sizeof(ulonglong2))       // 64KB
#define HBUF_U64 (128 * HPAD)                          // per buffer
#define LSTM_SMEM (U2_BYTES + 2 * HBUF_U64 * sizeof(u64t))

__global__ __launch_bounds__(128, 1) __cluster_dims__(4, 1, 1)
void lstm_kernel(const float* __restrict__ Ufw, const float* __restrict__ Ubw,
                 const float* __restrict__ bfw, const float* __restrict__ bbw,
                 float* __restrict__ out) {
    extern __shared__ char smem_raw[];
    ulonglong2 (*U2)[32] = (ulonglong2(*)[32])smem_raw;
    u64t* hbuf = (u64t*)(smem_raw + U2_BYTES);          // [2][128][HPAD]
    const uint32_t hbase = smem_u32(hbuf);

    const int bx = blockIdx.x;
    const int dir = bx >> 6, id = bx & 63;
    const int btile = id >> 2, utile = id & 3;
    const int tid = threadIdx.x, wid = tid >> 5, lane = tid & 31;
    const int ul = lane >> 2, bpair = lane & 3;
    const int ju = wid * 8 + ul;
    const int j = utile * 32 + ju;          // global unit 0..127
    const int bl0 = bpair * 2;
    const int b0 = btile * 8 + bl0, b1 = b0 + 1;

    const float* __restrict__ U    = dir ? Ubw : Ufw;
    const float* __restrict__ bias = dir ? bbw : bfw;

    // U2[k][m] gate pairs for unit (utile*32+m)
    {
        const int jg = utile * 32 + lane;
        for (int k = wid; k < 128; k += 4) {
            const float* up = U + (size_t)k * FOURH + jg;
            ulonglong2 v;
            v.x = pk2(up[0], up[128]);
            v.y = pk2(up[256], up[384]);
            U2[k][lane] = v;
        }
    }
    // zero both h buffers
    for (int q = tid; q < 2 * HBUF_U64; q += 128) hbuf[q] = 0ull;
    const u64t bz01 = pk2(bias[j], bias[Hh + j]);
    const u64t bz23 = pk2(bias[2 * Hh + j], bias[3 * Hh + j]);

    __syncthreads();
    CLUSTER_SYNC();   // peers' buffers zeroed before any DSMEM write lands

    float c0 = 0.0f, c1 = 0.0f, hout0 = 0.0f, hout1 = 0.0f;
    const size_t xw_dir = (size_t)dir * ((size_t)Tt * Bb * FOURH);
    // DSMEM target offsets for this thread's h values (unit j, batch bl0/bl0+1)
    const uint32_t hoff0 = (uint32_t)((j * HPAD + bl0) * sizeof(u64t));
    const uint32_t hoff1 = hoff0 + (uint32_t)sizeof(u64t);
    const uint32_t bufB = (uint32_t)(HBUF_U64 * sizeof(u64t));

    for (int t = 0; t < Tt; t++) {
        const int tt = dir ? (Tt - 1 - t) : t;
        const int p = t & 1;
        const u64t* __restrict__ hrd = hbuf + (size_t)p * HBUF_U64;

        const float* xwp = g_xw + xw_dir + ((size_t)tt * Bb) * FOURH;
        const float x00 = __ldg(xwp + (size_t)b0 * FOURH + j);
        const float x01 = __ldg(xwp + (size_t)b0 * FOURH + Hh + j);
        const float x02 = __ldg(xwp + (size_t)b0 * FOURH + 2 * Hh + j);
        const float x03 = __ldg(xwp + (size_t)b0 * FOURH + 3 * Hh + j);
        const float x10 = __ldg(xwp + (size_t)b1 * FOURH + j);
        const float x11 = __ldg(xwp + (size_t)b1 * FOURH + Hh + j);
        const float x12 = __ldg(xwp + (size_t)b1 * FOURH + 2 * Hh + j);
        const float x13 = __ldg(xwp + (size_t)b1 * FOURH + 3 * Hh + j);

        u64t acc01_0 = bz01, acc23_0 = bz23;
        u64t acc01_1 = bz01, acc23_1 = bz23;
#pragma unroll 16
        for (int k = 0; k < 128; k++) {
            const ulonglong2 u = U2[k][ju];
            const ulonglong2 hh = *(const ulonglong2*)(hrd + k * HPAD + bl0);
            FFMA2(acc01_0, hh.x, u.x);
            FFMA2(acc23_0, hh.x, u.y);
            FFMA2(acc01_1, hh.y, u.x);
            FFMA2(acc23_1, hh.y, u.y);
        }
        float a00, a01, a02, a03, a10, a11, a12, a13;
        upk2(acc01_0, a00, a01); upk2(acc23_0, a02, a03);
        upk2(acc01_1, a10, a11); upk2(acc23_1, a12, a13);
        a00 += x00; a01 += x01; a02 += x02; a03 += x03;
        a10 += x10; a11 += x11; a12 += x12; a13 += x13;
        {
            const float ig = sigmoid_f(a00), fg = sigmoid_f(a01);
            const float gg = tanh_f(a02), og = sigmoid_f(a03);
            c0 = fg * c0 + ig * gg;
            hout0 = og * tanh_f(c0);
        }
        {
            const float ig = sigmoid_f(a10), fg = sigmoid_f(a11);
            const float gg = tanh_f(a12), og = sigmoid_f(a13);
            c1 = fg * c1 + ig * gg;
            hout1 = og * tanh_f(c1);
        }

        // publish h into buffer p^1 of ALL 4 cluster CTAs (duplicated pairs)
        {
            const uint32_t wb = hbase + (p ? 0u : bufB);   // p^1 buffer
            const u64t v0 = pk2(hout0, hout0);
            const u64t v1 = pk2(hout1, hout1);
#pragma unroll
            for (int r = 0; r < 4; r++) {
                st_cluster_u64(wb + hoff0, r, v0);
                st_cluster_u64(wb + hoff1, r, v1);
            }
        }

        out[((size_t)b0 * Tt + tt) * 256 + dir * Hh + j] = hout0;
        out[((size_t)b1 * Tt + tt) * 256 + dir * Hh + j] = hout1;

        if (t < Tt - 1) CLUSTER_SYNC();
    }

    const size_t fin = (size_t)Bb * Tt * 256 + (size_t)dir * 2 * Bb * Hh;
    out[fin + (size_t)b0 * Hh + j] = hout0;
    out[fin + (size_t)b1 * Hh + j] = hout1;
    out[fin + Bb * Hh + (size_t)b0 * Hh + j] = c0;
    out[fin + Bb * Hh + (size_t)b1 * Hh + j] = c1;

    CLUSTER_SYNC();   // no CTA exits while peers may still DSMEM-write here
}

// ---------------- launch ----------------
extern "C" void kernel_launch(void* const* d_in, const int* in_sizes, int n_in,
                              void* d_out, int out_size) {
    const int*   tokens = (const int*)d_in[0];
    const float* emb    = (const float*)d_in[1];
    const float* Wfw    = (const float*)d_in[2];
    const float* Ufw    = (const float*)d_in[3];
    const float* bfw    = (const float*)d_in[4];
    const float* Wbw    = (const float*)d_in[5];
    const float* Ubw    = (const float*)d_in[6];
    const float* bbw    = (const float*)d_in[7];
    float* out = (float*)d_out;

    static bool attr_set = false;
    if (!attr_set) {
        cudaFuncSetAttribute(lstm_kernel, cudaFuncAttributeMaxDynamicSharedMemorySize, (int)LSTM_SMEM);
        attr_set = true;
    }

    conv_emb<<<(Vv * Ee + 255) / 256, 256>>>(emb);
    conv_w<<<(2 * KP * FOURH + 255) / 256, 256>>>(Wfw, Wbw);
    proj_mma<<<dim3(4, 512, 2), 256>>>(tokens);
    lstm_kernel<<<128, 128, LSTM_SMEM>>>(Ufw, Ubw, bfw, bbw, out);
}